// round 6
// baseline (speedup 1.0000x reference)
#include <cuda_runtime.h>

#define N_NODES 50000
#define N_EDGES 800000
#define D_FEAT  64
#define ROWS_PER_BLOCK 8

// Precomputed CSR row pointers.
__device__ int g_row_ptr[N_NODES + 1];

// Kernel A: O(E) scatter build of row_ptr from sorted row_idx.
// Thread t (1..E): fills ptr[r] = t for r in (row[t-1], row[t]] (row[E] := N).
// Thread 0: fills ptr[0..row[0]] = 0. Expected fill loop length ~N/E = 0.06.
__global__ __launch_bounds__(256)
void build_row_ptr_kernel(const int* __restrict__ row_idx) {
    const int t = blockIdx.x * blockDim.x + threadIdx.x;
    if (t > N_EDGES) return;
    if (t == 0) {
        const int r1 = __ldg(row_idx + 0);
        for (int r = 0; r <= r1; r++) g_row_ptr[r] = 0;
    } else {
        const int r0 = __ldg(row_idx + t - 1);
        const int r1 = (t < N_EDGES) ? __ldg(row_idx + t) : N_NODES;
        for (int r = r0 + 1; r <= r1; r++) g_row_ptr[r] = t;
    }
}

// Kernel B: warp-per-row SpMM. 16 lanes x float4 per row; half-warps process
// edges e (lanes 0-15) and e+1 (lanes 16-31) in the same LDG.128.
// Metadata (col/val) staged once per 32 edges via one coalesced LDG each and
// distributed with shfl -> metadata LDG cost drops 16x. Phantom values are
// zeroed once at stage time.
__global__ __launch_bounds__(ROWS_PER_BLOCK * 32)
void gcn_spmm_kernel(const int* __restrict__ col_idx,
                     const float* __restrict__ vals,
                     const float* __restrict__ embeds,
                     float* __restrict__ out) {
    const int tid  = threadIdx.x;
    const int wid  = tid >> 5;
    const int lane = tid & 31;
    const int half = lane >> 4;         // 0: even edge of pair, 1: odd edge
    const int l16  = lane & 15;         // float4 group within the row
    const int row  = blockIdx.x * ROWS_PER_BLOCK + wid;

    const int start = __ldg(&g_row_ptr[row]);
    const int end   = __ldg(&g_row_ptr[row + 1]);
    const int npairs = (end - start + 1) >> 1;

    const float4* __restrict__ emb4 = reinterpret_cast<const float4*>(embeds);

    float4 acc = make_float4(0.0f, 0.0f, 0.0f, 0.0f);

    for (int p0 = 0; p0 < npairs; p0 += 16) {       // 16 pairs = 32 edges
        const int eb = start + 2 * p0;
        // Stage 32 edges of metadata: 2 coalesced LDGs per warp.
        const int eidx = eb + lane;
        const int idx  = min(eidx, end - 1);        // loop ran => end > start
        const int   c32 = __ldg(col_idx + idx);
        const float vld = __ldg(vals + idx);
        const float v32 = (eidx < end) ? vld : 0.0f;  // phantom -> 0 here once

        const int plim = min(npairs - p0, 16);
        int p = 0;
        // Main: blocks of 4 pairs, gathers batched (MLP=4 per warp).
        for (; p + 4 <= plim; p += 4) {
            int    c[4];
            float  v[4];
            float4 x[4];
            #pragma unroll
            for (int i = 0; i < 4; i++) {
                const int src = 2 * (p + i) + half;
                c[i] = __shfl_sync(0xffffffffu, c32, src);
                v[i] = __shfl_sync(0xffffffffu, v32, src);
                x[i] = __ldg(emb4 + (size_t)c[i] * 16 + l16);
            }
            #pragma unroll
            for (int i = 0; i < 4; i++) {
                acc.x = fmaf(v[i], x[i].x, acc.x);
                acc.y = fmaf(v[i], x[i].y, acc.y);
                acc.z = fmaf(v[i], x[i].z, acc.z);
                acc.w = fmaf(v[i], x[i].w, acc.w);
            }
        }
        // Tail: <=3 pairs, serial (phantom gathers limited to the odd edge).
        for (; p < plim; p++) {
            const int src = 2 * p + half;
            const int   c = __shfl_sync(0xffffffffu, c32, src);
            const float v = __shfl_sync(0xffffffffu, v32, src);
            const float4 x = __ldg(emb4 + (size_t)c * 16 + l16);
            acc.x = fmaf(v, x.x, acc.x);
            acc.y = fmaf(v, x.y, acc.y);
            acc.z = fmaf(v, x.z, acc.z);
            acc.w = fmaf(v, x.w, acc.w);
        }
    }

    // Fold odd-edge half into even half; lanes 0-15 store the 256B row.
    acc.x += __shfl_down_sync(0xffffffffu, acc.x, 16);
    acc.y += __shfl_down_sync(0xffffffffu, acc.y, 16);
    acc.z += __shfl_down_sync(0xffffffffu, acc.z, 16);
    acc.w += __shfl_down_sync(0xffffffffu, acc.w, 16);
    if (half == 0)
        reinterpret_cast<float4*>(out)[(size_t)row * 16 + l16] = acc;
}

extern "C" void kernel_launch(void* const* d_in, const int* in_sizes, int n_in,
                              void* d_out, int out_size) {
    const int*   row_idx = (const int*)  d_in[0];
    const int*   col_idx = (const int*)  d_in[1];
    const float* vals    = (const float*)d_in[2];
    const float* embeds  = (const float*)d_in[3];
    float*       out     = (float*)d_out;

    build_row_ptr_kernel<<<(N_EDGES + 1 + 255) / 256, 256>>>(row_idx);

    const int blocks = N_NODES / ROWS_PER_BLOCK;   // 6250
    gcn_spmm_kernel<<<blocks, ROWS_PER_BLOCK * 32>>>(col_idx, vals, embeds, out);
}